// round 2
// baseline (speedup 1.0000x reference)
#include <cuda_runtime.h>

#define NN 100000
#define EE 1600000
#define NTILES (EE / 128)   // 12500, exact

// Scratch (no allocs allowed): per-node precomputed partial activations.
__device__ __align__(256) float g_A[NN * 64];     // (W1a - W1b) @ x[n] + b1
__device__ __align__(256) float g_B[NN * 64];     // W1b @ x[n]
__device__ __align__(256) float g_WcT[64 * 128];  // [k][j] combined layer-1 weight, transposed
__device__ __align__(256) float g_W2T[64 * 64];   // [k][j] = W2[j][k]

// ---------------------------------------------------------------------------
// Weight prep: build transposed/combined weight matrices.
// ---------------------------------------------------------------------------
__global__ void prep_kernel(const float* __restrict__ W1,
                            const float* __restrict__ W2) {
    int t = threadIdx.x;
    for (int idx = t; idx < 64 * 128; idx += blockDim.x) {
        int k = idx >> 7, j = idx & 127;
        float v;
        if (j < 64) v = W1[j * 128 + k] - W1[j * 128 + 64 + k];
        else        v = W1[(j - 64) * 128 + 64 + k];
        g_WcT[idx] = v;
    }
    for (int idx = t; idx < 64 * 64; idx += blockDim.x) {
        int k = idx >> 6, j = idx & 63;
        g_W2T[idx] = W2[j * 64 + k];
    }
}

// ---------------------------------------------------------------------------
// Precompute A[n], B[n]: [N,64] x [64,128] GEMM, tiled 64 nodes/block.
// Thread micro-tile: 8 nodes x 4 outputs (of 128).
// ---------------------------------------------------------------------------
#define XS_STRIDE 68

__global__ void __launch_bounds__(256, 2)
pre_kernel(const float* __restrict__ x, const float* __restrict__ b1) {
    extern __shared__ float sm[];
    float* Ws = sm;            // 64*128 = 8192 floats
    float* xs = sm + 8192;     // 64*68  = 4352 floats

    int t = threadIdx.x;
    int n0 = blockIdx.x * 64;

    for (int i = t; i < 2048; i += 256)
        ((float4*)Ws)[i] = ((const float4*)g_WcT)[i];

    for (int i = t; i < 1024; i += 256) {
        int nl = i >> 4;
        int k  = (i & 15) << 2;
        int node = n0 + nl;
        float4 v = make_float4(0.f, 0.f, 0.f, 0.f);
        if (node < NN) v = *(const float4*)(x + node * 64 + k);
        *(float4*)(xs + nl * XS_STRIDE + k) = v;
    }
    __syncthreads();

    int jg = t & 31;  int j  = jg << 2;   // output col 0..124
    int ng = t >> 5;  int nb = ng << 3;   // node base 0..56

    float acc[8][4];
#pragma unroll
    for (int i = 0; i < 8; i++)
#pragma unroll
        for (int c = 0; c < 4; c++) acc[i][c] = 0.f;

#pragma unroll 4
    for (int k = 0; k < 64; k += 4) {
        float4 w0 = *(float4*)(Ws + (k + 0) * 128 + j);
        float4 w1 = *(float4*)(Ws + (k + 1) * 128 + j);
        float4 w2 = *(float4*)(Ws + (k + 2) * 128 + j);
        float4 w3 = *(float4*)(Ws + (k + 3) * 128 + j);
#pragma unroll
        for (int i = 0; i < 8; i++) {
            float4 xv = *(float4*)(xs + (nb + i) * XS_STRIDE + k);
            acc[i][0] = fmaf(xv.x, w0.x, acc[i][0]);
            acc[i][1] = fmaf(xv.x, w0.y, acc[i][1]);
            acc[i][2] = fmaf(xv.x, w0.z, acc[i][2]);
            acc[i][3] = fmaf(xv.x, w0.w, acc[i][3]);
            acc[i][0] = fmaf(xv.y, w1.x, acc[i][0]);
            acc[i][1] = fmaf(xv.y, w1.y, acc[i][1]);
            acc[i][2] = fmaf(xv.y, w1.z, acc[i][2]);
            acc[i][3] = fmaf(xv.y, w1.w, acc[i][3]);
            acc[i][0] = fmaf(xv.z, w2.x, acc[i][0]);
            acc[i][1] = fmaf(xv.z, w2.y, acc[i][1]);
            acc[i][2] = fmaf(xv.z, w2.z, acc[i][2]);
            acc[i][3] = fmaf(xv.z, w2.w, acc[i][3]);
            acc[i][0] = fmaf(xv.w, w3.x, acc[i][0]);
            acc[i][1] = fmaf(xv.w, w3.y, acc[i][1]);
            acc[i][2] = fmaf(xv.w, w3.z, acc[i][2]);
            acc[i][3] = fmaf(xv.w, w3.w, acc[i][3]);
        }
    }

#pragma unroll
    for (int i = 0; i < 8; i++) {
        int node = n0 + nb + i;
        if (node < NN) {
            float4 o;
            if (j < 64) {
                float4 bv = __ldg((const float4*)(b1 + j));
                o.x = acc[i][0] + bv.x;
                o.y = acc[i][1] + bv.y;
                o.z = acc[i][2] + bv.z;
                o.w = acc[i][3] + bv.w;
                *(float4*)(g_A + node * 64 + j) = o;
            } else {
                o.x = acc[i][0]; o.y = acc[i][1];
                o.z = acc[i][2]; o.w = acc[i][3];
                *(float4*)(g_B + node * 64 + (j - 64)) = o;
            }
        }
    }
}

// ---------------------------------------------------------------------------
// Edge kernel: per 128-edge tile, gather h = relu(A[row] + B[col]) into SMEM,
// then tiled GEMM with W2^T (in SMEM). Thread micro-tile: 8 edges x 4 outs.
// NOTE: edge_index is int32 (JAX x64 disabled -> int64 request yields int32).
// ---------------------------------------------------------------------------
#define HS_STRIDE 68

__global__ void __launch_bounds__(256, 2)
edge_kernel(const int* __restrict__ ei,
            const float* __restrict__ b2,
            float* __restrict__ out) {
    extern __shared__ float sm[];
    float* W2s = sm;            // 64*64  = 4096 floats
    float* hs  = sm + 4096;     // 128*68 = 8704 floats

    int t = threadIdx.x;
    for (int i = t; i < 1024; i += 256)
        ((float4*)W2s)[i] = ((const float4*)g_W2T)[i];

    int jt = t & 15;  int j  = jt << 2;    // out col 0..60
    int eg = t >> 4;  int eb = eg << 3;    // edge base 0..120

    int he = t & 127;                      // h-phase edge
    int hk = (t >> 7) << 5;                // h-phase k base: 0 or 32

    float4 bb = __ldg((const float4*)(b2 + j));

    for (int tile = blockIdx.x; tile < NTILES; tile += gridDim.x) {
        int ebase = tile * 128;
        __syncthreads();   // protect hs from previous tile's readers

        // ---- h phase: 2 threads per edge, 32 k each ----
        {
            int e = ebase + he;
            int r = __ldg(ei + e);
            int c = __ldg(ei + EE + e);
            const float* Ar = g_A + r * 64 + hk;
            const float* Bc = g_B + c * 64 + hk;
            float* hrow = hs + he * HS_STRIDE + hk;
#pragma unroll
            for (int q = 0; q < 8; q++) {
                float4 a = __ldg((const float4*)(Ar + q * 4));
                float4 b = __ldg((const float4*)(Bc + q * 4));
                float4 h;
                h.x = fmaxf(a.x + b.x, 0.f);
                h.y = fmaxf(a.y + b.y, 0.f);
                h.z = fmaxf(a.z + b.z, 0.f);
                h.w = fmaxf(a.w + b.w, 0.f);
                *(float4*)(hrow + q * 4) = h;
            }
        }
        __syncthreads();

        // ---- GEMM phase: out[e][j] = relu(sum_k h[e][k] * W2T[k][j] + b2[j])
        float acc[8][4];
#pragma unroll
        for (int i = 0; i < 8; i++)
#pragma unroll
            for (int c = 0; c < 4; c++) acc[i][c] = 0.f;

#pragma unroll 4
        for (int k = 0; k < 64; k += 4) {
            float4 w0 = *(float4*)(W2s + (k + 0) * 64 + j);
            float4 w1 = *(float4*)(W2s + (k + 1) * 64 + j);
            float4 w2 = *(float4*)(W2s + (k + 2) * 64 + j);
            float4 w3 = *(float4*)(W2s + (k + 3) * 64 + j);
#pragma unroll
            for (int i = 0; i < 8; i++) {
                float4 hv = *(float4*)(hs + (eb + i) * HS_STRIDE + k);
                acc[i][0] = fmaf(hv.x, w0.x, acc[i][0]);
                acc[i][1] = fmaf(hv.x, w0.y, acc[i][1]);
                acc[i][2] = fmaf(hv.x, w0.z, acc[i][2]);
                acc[i][3] = fmaf(hv.x, w0.w, acc[i][3]);
                acc[i][0] = fmaf(hv.y, w1.x, acc[i][0]);
                acc[i][1] = fmaf(hv.y, w1.y, acc[i][1]);
                acc[i][2] = fmaf(hv.y, w1.z, acc[i][2]);
                acc[i][3] = fmaf(hv.y, w1.w, acc[i][3]);
                acc[i][0] = fmaf(hv.z, w2.x, acc[i][0]);
                acc[i][1] = fmaf(hv.z, w2.y, acc[i][1]);
                acc[i][2] = fmaf(hv.z, w2.z, acc[i][2]);
                acc[i][3] = fmaf(hv.z, w2.w, acc[i][3]);
                acc[i][0] = fmaf(hv.w, w3.x, acc[i][0]);
                acc[i][1] = fmaf(hv.w, w3.y, acc[i][1]);
                acc[i][2] = fmaf(hv.w, w3.z, acc[i][2]);
                acc[i][3] = fmaf(hv.w, w3.w, acc[i][3]);
            }
        }

#pragma unroll
        for (int i = 0; i < 8; i++) {
            float4 o;
            o.x = fmaxf(acc[i][0] + bb.x, 0.f);
            o.y = fmaxf(acc[i][1] + bb.y, 0.f);
            o.z = fmaxf(acc[i][2] + bb.z, 0.f);
            o.w = fmaxf(acc[i][3] + bb.w, 0.f);
            *(float4*)(out + (size_t)(ebase + eb + i) * 64 + j) = o;
        }
    }
}

// ---------------------------------------------------------------------------
extern "C" void kernel_launch(void* const* d_in, const int* in_sizes, int n_in,
                              void* d_out, int out_size) {
    const float* x  = (const float*)d_in[0];
    const int*   ei = (const int*)d_in[1];     // int32 (JAX x64 disabled)
    const float* W1 = (const float*)d_in[2];
    const float* b1 = (const float*)d_in[3];
    const float* W2 = (const float*)d_in[4];
    const float* b2 = (const float*)d_in[5];
    float*       out = (float*)d_out;

    const int PRE_SMEM  = (8192 + 64 * XS_STRIDE) * 4;     // 50176 B
    const int EDGE_SMEM = (4096 + 128 * HS_STRIDE) * 4;    // 51200 B

    cudaFuncSetAttribute(pre_kernel,
                         cudaFuncAttributeMaxDynamicSharedMemorySize, PRE_SMEM);
    cudaFuncSetAttribute(edge_kernel,
                         cudaFuncAttributeMaxDynamicSharedMemorySize, EDGE_SMEM);

    prep_kernel<<<1, 256>>>(W1, W2);
    pre_kernel<<<(NN + 63) / 64, 256, PRE_SMEM>>>(x, b1);
    edge_kernel<<<1250, 256, EDGE_SMEM>>>(ei, b2, out);
}